// round 5
// baseline (speedup 1.0000x reference)
#include <cuda_runtime.h>
#include <math.h>

#define BB 2
#define LL 225
#define DD 256
#define HH 4
#define HD 64
#define BH 8
#define NROW 450
#define LP 240

// ---------------- scratch ----------------------------------------------------
__device__ __align__(16) float g_q[BH*LL*HD];
__device__ __align__(16) float g_k[BH*LL*HD];
__device__ __align__(16) float g_v[BH*LL*HD];
__device__ __align__(16) float g_S[BH*LL*LP + 16];
__device__ __align__(16) float g_A[BH*LL*LP + 16];
__device__ __align__(16) float g_T[BH*LL*LP + 16];
__device__ __align__(16) float g_P[BH*LL*LP + 16];
__device__ __align__(16) float g_O[NROW*DD];
__device__ float g_deg[BH*LP];

// ---------------- helpers -----------------------------------------------------
__device__ __forceinline__ float4 ld4(const float* p) { return *(const float4*)p; }
__device__ __forceinline__ float4 f4z() { return make_float4(0.f, 0.f, 0.f, 0.f); }

__device__ __forceinline__ unsigned long long pk2(float lo, float hi) {
    unsigned long long r;
    asm("mov.b64 %0,{%1,%2};" : "=l"(r) : "f"(lo), "f"(hi));
    return r;
}
__device__ __forceinline__ void fma2(unsigned long long& d,
                                     unsigned long long a, unsigned long long b) {
    asm("fma.rn.f32x2 %0,%1,%2,%0;" : "+l"(d) : "l"(a), "l"(b));
}
__device__ __forceinline__ unsigned long long mul2(unsigned long long a,
                                                   unsigned long long b) {
    unsigned long long r;
    asm("mul.rn.f32x2 %0,%1,%2;" : "=l"(r) : "l"(a), "l"(b));
    return r;
}
__device__ __forceinline__ float2 up2(unsigned long long v) {
    float2 f;
    asm("mov.b64 {%0,%1},%2;" : "=f"(f.x), "=f"(f.y) : "l"(v));
    return f;
}

// C[4][4] += A(.. x16, stride AST) * B(16 x .., stride BST), packed f32x2
template<int AST, int BST>
__device__ __forceinline__ void inner16(const float* As, const float* Bs,
                                        int ty4, int tx4, unsigned long long acc[4][2]) {
#pragma unroll
    for (int kk = 0; kk < 16; kk++) {
        float4 bv = *(const float4*)(Bs + kk*BST + tx4);
        unsigned long long b01 = pk2(bv.x, bv.y);
        unsigned long long b23 = pk2(bv.z, bv.w);
#pragma unroll
        for (int r = 0; r < 4; r++) {
            float ar = As[(ty4 + r)*AST + kk];
            unsigned long long aa = pk2(ar, ar);
            fma2(acc[r][0], aa, b01);
            fma2(acc[r][1], aa, b23);
        }
    }
}

// C[2][4] variant for 32-row tiles
template<int AST, int BST>
__device__ __forceinline__ void inner16_2(const float* As, const float* Bs,
                                          int ty2, int tx4, unsigned long long acc[2][2]) {
#pragma unroll
    for (int kk = 0; kk < 16; kk++) {
        float4 bv = *(const float4*)(Bs + kk*BST + tx4);
        unsigned long long b01 = pk2(bv.x, bv.y);
        unsigned long long b23 = pk2(bv.z, bv.w);
#pragma unroll
        for (int r = 0; r < 2; r++) {
            float ar = As[(ty2 + r)*AST + kk];
            unsigned long long aa = pk2(ar, ar);
            fma2(acc[r][0], aa, b01);
            fma2(acc[r][1], aa, b23);
        }
    }
}

// ---------------- K1: qkv projections (y = x @ W^T) ---------------------------
// grid (12, 15), block (16, 8). tile 32 rows x 64 cols; cols 0..767 = [Wq|Wk|Wv]
__global__ void qkv_kernel(const float* __restrict__ x,
                           const float* __restrict__ Wq,
                           const float* __restrict__ Wk,
                           const float* __restrict__ Wv) {
    __shared__ __align__(16) float Xs[32][20];
    __shared__ __align__(16) float Ws[16][68];
    int tx = threadIdx.x, ty = threadIdx.y;
    int tid = ty*16 + tx;                 // 0..127
    int m0 = blockIdx.y * 32;
    int c0 = blockIdx.x * 64;
    const float* W = (c0 < 256) ? Wq : (c0 < 512) ? Wk : Wv;
    int cw0 = c0 & 255;
    unsigned long long acc[4][2] = {};
    for (int k0 = 0; k0 < 256; k0 += 16) {
        { int ii = tid >> 2, f = tid & 3;
          int m = m0 + ii;
          float4 v = (m < NROW) ? ld4(x + m*256 + k0 + 4*f) : f4z();
          *(float4*)&Xs[ii][4*f] = v; }
#pragma unroll
        for (int s = 0; s < 2; s++) {
            int idx = tid + 128*s;
            int ll = idx >> 2, g = idx & 3;
            float4 w = ld4(W + (cw0 + ll)*256 + k0 + 4*g);
            Ws[4*g+0][ll] = w.x; Ws[4*g+1][ll] = w.y;
            Ws[4*g+2][ll] = w.z; Ws[4*g+3][ll] = w.w;
        }
        __syncthreads();
        inner16<20, 68>(&Xs[0][0], &Ws[0][0], ty*4, tx*4, acc);
        __syncthreads();
    }
    int which = c0 >> 8, hb = (c0 & 255) >> 6;
    float* dst = (which == 0) ? g_q : (which == 1) ? g_k : g_v;
#pragma unroll
    for (int r = 0; r < 4; r++) {
        int m = m0 + ty*4 + r;
        if (m < NROW) {
            int b = (m >= LL) ? 1 : 0;
            int l = m - b*LL;
            float2 lo = up2(acc[r][0]), hi = up2(acc[r][1]);
            *(float4*)(dst + ((b*HH + hb)*LL + l)*HD + tx*4) =
                make_float4(lo.x, lo.y, hi.x, hi.y);
        }
    }
}

// ---------------- K2: S = q @ k^T per (b,h), also zero g_deg -------------------
// grid (4, 4, 8), block (16,16). tile 64x64, K=64.
__global__ void s_kernel() {
    __shared__ __align__(16) float Qs[64][20];
    __shared__ __align__(16) float Ks[16][68];
    int tx = threadIdx.x, ty = threadIdx.y;
    int tid = ty*16 + tx;
    int bh = blockIdx.z;
    if (blockIdx.x == 0 && blockIdx.y == 0 && tid < LP) g_deg[bh*LP + tid] = 0.f;
    int i0 = blockIdx.y*64, j0 = blockIdx.x*64;
    const float* qb = g_q + bh*LL*HD;
    const float* kb = g_k + bh*LL*HD;
    unsigned long long acc[4][2] = {};
#pragma unroll
    for (int d0 = 0; d0 < 64; d0 += 16) {
        { int ii = tid >> 2, f = tid & 3;
          int i = i0 + ii;
          float4 v = (i < LL) ? ld4(qb + i*HD + d0 + 4*f) : f4z();
          *(float4*)&Qs[ii][4*f] = v; }
        { int ll = tid >> 2, f = tid & 3;
          int j = j0 + ll;
          float4 v = (j < LL) ? ld4(kb + j*HD + d0 + 4*f) : f4z();
          Ks[4*f+0][ll] = v.x; Ks[4*f+1][ll] = v.y;
          Ks[4*f+2][ll] = v.z; Ks[4*f+3][ll] = v.w; }
        __syncthreads();
        inner16<20, 68>(&Qs[0][0], &Ks[0][0], ty*4, tx*4, acc);
        __syncthreads();
    }
    float* Sb = g_S + bh*LL*LP;
    int jc = j0 + tx*4;
    if (jc < LP) {
#pragma unroll
        for (int r = 0; r < 4; r++) {
            int i = i0 + ty*4 + r;
            if (i < LL) {
                float2 lo = up2(acc[r][0]), hi = up2(acc[r][1]);
                *(float4*)(Sb + i*LP + jc) = make_float4(lo.x, lo.y, hi.x, hi.y);
            }
        }
    }
}

// ---------------- K3: adjacency, 32x32 symmetric tile pairs + fused deg --------
// grid (36, 8), block (16,16). Double-buffered, dup-Si, packed muls.
__global__ void a_kernel() {
    __shared__ __align__(16) float2 SiD[2][16][34];
    __shared__ __align__(16) float  SkT[2][16][36];
    __shared__ float scol[32];
    int tx = threadIdx.x, ty = threadIdx.y;
    int tid = ty*16 + tx;
    int p = blockIdx.x, bh = blockIdx.y;
    int ti = 0, rem = p;
    while (rem >= 8 - ti) { rem -= 8 - ti; ti++; }
    int tk = ti + rem;
    int i0 = ti*32, k0 = tk*32;
    const float* Sb = g_S + bh*LL*LP;
    const float THR = 6.4f;   // == 0.1f * 64 exactly in fp32
    if (tid < 32) scol[tid] = 0.f;

    int lr = (tid & 127) >> 2;        // 0..31
    int af = (tid & 3) * 4;           // 0,4,8,12
    bool isA = tid < 128;
    int lrow = (isA ? i0 : k0) + lr;
    float4 reg;

    float a00 = 0.f, a01 = 0.f, a10 = 0.f, a11 = 0.f;

    // prologue: chunk 0
    reg = (lrow < LL) ? ld4(Sb + lrow*LP + af) : f4z();
    if (isA) {
        SiD[0][af+0][lr] = make_float2(reg.x, reg.x);
        SiD[0][af+1][lr] = make_float2(reg.y, reg.y);
        SiD[0][af+2][lr] = make_float2(reg.z, reg.z);
        SiD[0][af+3][lr] = make_float2(reg.w, reg.w);
    } else {
        SkT[0][af+0][lr] = reg.x; SkT[0][af+1][lr] = reg.y;
        SkT[0][af+2][lr] = reg.z; SkT[0][af+3][lr] = reg.w;
    }
    __syncthreads();

    for (int c = 0; c < 15; c++) {
        int st = c & 1;
        if (c < 14)
            reg = (lrow < LL) ? ld4(Sb + lrow*LP + (c+1)*16 + af) : f4z();
#pragma unroll
        for (int kk = 0; kk < 16; kk++) {
            ulonglong2 a = *(const ulonglong2*)&SiD[st][kk][ty*2];
            unsigned long long b = *(const unsigned long long*)&SkT[st][kk][tx*2];
            float2 f0 = up2(mul2(a.x, b));
            float2 f1 = up2(mul2(a.y, b));
            if (f0.x > THR) a00 += f0.x;
            if (f0.y > THR) a01 += f0.y;
            if (f1.x > THR) a10 += f1.x;
            if (f1.y > THR) a11 += f1.y;
        }
        if (c < 14) {
            int s2 = st ^ 1;
            if (isA) {
                SiD[s2][af+0][lr] = make_float2(reg.x, reg.x);
                SiD[s2][af+1][lr] = make_float2(reg.y, reg.y);
                SiD[s2][af+2][lr] = make_float2(reg.z, reg.z);
                SiD[s2][af+3][lr] = make_float2(reg.w, reg.w);
            } else {
                SkT[s2][af+0][lr] = reg.x; SkT[s2][af+1][lr] = reg.y;
                SkT[s2][af+2][lr] = reg.z; SkT[s2][af+3][lr] = reg.w;
            }
        }
        __syncthreads();
    }

    const float sc = 1.f / (64.f * 225.f);
    int ig0 = i0 + ty*2, kg0 = k0 + tx*2;
    float av[2][2] = {{a00*sc, a01*sc}, {a10*sc, a11*sc}};
#pragma unroll
    for (int r = 0; r < 2; r++)
#pragma unroll
        for (int c = 0; c < 2; c++)
            if (ig0 + r == kg0 + c) av[r][c] = 0.f;
    float* Ab = g_A + bh*LL*LP;
#pragma unroll
    for (int r = 0; r < 2; r++) {
        int ig = ig0 + r;
        if (ig < LL) {
#pragma unroll
            for (int c = 0; c < 2; c++) {
                int kg = kg0 + c;
                if (kg < LP) Ab[ig*LP + kg] = av[r][c];
            }
        }
    }
    if (ti != tk) {
#pragma unroll
        for (int c = 0; c < 2; c++) {
            int kg = kg0 + c;
            if (kg < LL) {
#pragma unroll
                for (int r = 0; r < 2; r++) {
                    int ig = ig0 + r;
                    if (ig < LP) Ab[kg*LP + ig] = av[r][c];
                }
            }
        }
    }
#pragma unroll
    for (int r = 0; r < 2; r++) {
        float rs = av[r][0] + av[r][1];
#pragma unroll
        for (int off = 8; off > 0; off >>= 1)
            rs += __shfl_xor_sync(0xffffffffu, rs, off);
        int ig = ig0 + r;
        if (tx == 0 && ig < LL) atomicAdd(&g_deg[bh*LP + ig], rs);
    }
    if (ti != tk) {
#pragma unroll
        for (int c = 0; c < 2; c++) {
            float cs = av[0][c] + av[1][c];
            atomicAdd(&scol[tx*2 + c], cs);
        }
        __syncthreads();
        if (tid < 32) {
            int kg = k0 + tid;
            if (kg < LL) atomicAdd(&g_deg[bh*LP + kg], scol[tid]);
        }
    }
}

// ---------------- K4/K5: 225^3 GEMMs, double-buffered, dup-A, A_hat on the fly --
// MODE 0: T = A_hat @ S        MODE 1: P = T @ A_hat / 8  (A_hat symmetric)
// grid (4 j, 8 i, 8 bh), block (16,16). Tile 32(M) x 64(N).
template<int MODE>
__global__ void gemm_kernel() {
    __shared__ __align__(16) float2 AsD[2][16][34];
    __shared__ __align__(16) float  Bs[2][16][68];
    __shared__ float sdis[LP];
    int tx = threadIdx.x, ty = threadIdx.y;
    int tid = ty*16 + tx;
    int bh = blockIdx.z;
    int i0 = blockIdx.y*32, j0 = blockIdx.x*64;
    if (tid < LP) sdis[tid] = rsqrtf(fmaxf(1.f + g_deg[bh*LP + tid], 1e-6f));
    const float* Aop = ((MODE == 0) ? g_A : g_T) + bh*LL*LP;
    const float* Bop = ((MODE == 0) ? g_S : g_A) + bh*LL*LP;
    float*       Cb  = ((MODE == 0) ? g_T : g_P) + bh*LL*LP;
    __syncthreads();

    bool isA = tid < 128;
    int alr = tid >> 2;               // valid when isA: 0..31
    int aaf = (tid & 3) * 4;
    int arow = i0 + (isA ? alr : 0);
    int bkk = tid >> 4, bj4 = (tid & 15) * 4;
    int bj = j0 + bj4;

    float4 aReg = f4z(), bReg;

    auto loadc = [&](int c) {
        if (isA)
            aReg = (arow < LL) ? ld4(Aop + arow*LP + c*16 + aaf) : f4z();
        int k = c*16 + bkk;
        bReg = (k < LL && bj < LP) ? ld4(Bop + k*LP + bj) : f4z();
    };
    auto storec = [&](int st, int c) {
        if (isA) {
            float4 v = aReg;
            if (MODE == 0) {
                int kb = c*16 + aaf;
                float4 dk = *(const float4*)&sdis[kb];
                v.x *= dk.x; v.y *= dk.y; v.z *= dk.z; v.w *= dk.w;
                if (arow < LL) {
                    int dj = arow - kb;
                    if (dj == 0) v.x += dk.x; else if (dj == 1) v.y += dk.y;
                    else if (dj == 2) v.z += dk.z; else if (dj == 3) v.w += dk.w;
                }
            }
            AsD[st][aaf+0][alr] = make_float2(v.x, v.x);
            AsD[st][aaf+1][alr] = make_float2(v.y, v.y);
            AsD[st][aaf+2][alr] = make_float2(v.z, v.z);
            AsD[st][aaf+3][alr] = make_float2(v.w, v.w);
        }
        {
            float4 v = bReg;
            if (MODE == 1) {
                int k = c*16 + bkk;
                float dk = (k < LL) ? sdis[k] : 0.f;
                v.x *= dk; v.y *= dk; v.z *= dk; v.w *= dk;
                int dj = k - bj;
                if (dj == 0) v.x += dk; else if (dj == 1) v.y += dk;
                else if (dj == 2) v.z += dk; else if (dj == 3) v.w += dk;
            }
            *(float4*)&Bs[st][bkk][bj4] = v;
        }
    };

    unsigned long long acc[2][2] = {};
    loadc(0); storec(0, 0); __syncthreads();
    for (int c = 0; c < 15; c++) {
        int st = c & 1;
        if (c < 14) loadc(c + 1);
#pragma unroll
        for (int kk = 0; kk < 16; kk++) {
            ulonglong2 a = *(const ulonglong2*)&AsD[st][kk][ty*2];
            ulonglong2 b = *(const ulonglong2*)&Bs[st][kk][tx*4];
            fma2(acc[0][0], a.x, b.x); fma2(acc[0][1], a.x, b.y);
            fma2(acc[1][0], a.y, b.x); fma2(acc[1][1], a.y, b.y);
        }
        if (c < 14) storec(st ^ 1, c + 1);
        __syncthreads();
    }

    int jc = j0 + tx*4;
    if (jc < LP) {
        float4 sj = make_float4(1.f, 1.f, 1.f, 1.f);
        if (MODE == 1) sj = *(const float4*)&sdis[jc];
#pragma unroll
        for (int r = 0; r < 2; r++) {
            int i = i0 + ty*2 + r;
            if (i < LL) {
                float2 lo = up2(acc[r][0]), hi = up2(acc[r][1]);
                float4 o = make_float4(lo.x, lo.y, hi.x, hi.y);
                if (MODE == 0) {
                    float di = sdis[i];
                    o.x *= di; o.y *= di; o.z *= di; o.w *= di;
                } else {
                    o.x *= sj.x * 0.125f; o.y *= sj.y * 0.125f;
                    o.z *= sj.z * 0.125f; o.w *= sj.w * 0.125f;
                }
                *(float4*)(Cb + i*LP + jc) = o;
            }
        }
    }
}

// ---------------- K6: fused softmax + O = attn @ v ------------------------------
// grid (8, 8), block (16,16). 32-row tiles, 64 output cols (= HD).
__global__ void av_kernel() {
    __shared__ __align__(16) float Ps[32][20];
    __shared__ __align__(16) float Vs[16][68];
    __shared__ float smx[32], sinv[32];
    int tx = threadIdx.x, ty = threadIdx.y;
    int tid = ty*16 + tx;
    int bh = blockIdx.y;
    int i0 = blockIdx.x*32;
    const float* Pb = g_P + bh*LL*LP;
    const float* Vb = g_v + bh*LL*HD;
    {
        int w = tid >> 5, lane = tid & 31;
#pragma unroll
        for (int rr = 0; rr < 4; rr++) {
            int row = w*4 + rr;
            int i = i0 + row;
            if (i < LL) {
                const float* Pr = Pb + i*LP;
                float vb[8];
                float m = -1e30f;
#pragma unroll
                for (int e = 0; e < 8; e++) {
                    int j = lane + 32*e;
                    float v = (j < LL) ? Pr[j] : -1e30f;
                    vb[e] = v;
                    m = fmaxf(m, v);
                }
#pragma unroll
                for (int off = 16; off > 0; off >>= 1)
                    m = fmaxf(m, __shfl_xor_sync(0xffffffffu, m, off));
                float s = 0.f;
#pragma unroll
                for (int e = 0; e < 8; e++) s += __expf(vb[e] - m);
#pragma unroll
                for (int off = 16; off > 0; off >>= 1)
                    s += __shfl_xor_sync(0xffffffffu, s, off);
                if (lane == 0) { smx[row] = m; sinv[row] = 1.f / s; }
            }
        }
    }
    __syncthreads();
    unsigned long long acc[2][2] = {};
    for (int k0 = 0; k0 < LP; k0 += 16) {
        if (tid < 128) {
            int ii = tid >> 2, f = tid & 3;
            int i = i0 + ii;
            float4 v;
            if (i < LL) {
                v = ld4(Pb + i*LP + k0 + 4*f);
                float m = smx[ii], inv = sinv[ii];
                int kb = k0 + 4*f;
                v.x = (kb + 0 < LL) ? __expf(v.x - m)*inv : 0.f;
                v.y = (kb + 1 < LL) ? __expf(v.y - m)*inv : 0.f;
                v.z = (kb + 2 < LL) ? __expf(v.z - m)*inv : 0.f;
                v.w = (kb + 3 < LL) ? __expf(v.w - m)*inv : 0.f;
            } else v = f4z();
            *(float4*)&Ps[ii][4*f] = v;
        } else {
#pragma unroll
            for (int s2 = 0; s2 < 2; s2++) {
                int idx = (tid - 128) + 128*s2;
                int kk = idx >> 4, d4 = (idx & 15)*4;
                int k = k0 + kk;
                float4 v = (k < LL) ? ld4(Vb + k*HD + d4) : f4z();
                *(float4*)&Vs[kk][d4] = v;
            }
        }
        __syncthreads();
        inner16_2<20, 68>(&Ps[0][0], &Vs[0][0], ty*2, tx*4, acc);
        __syncthreads();
    }
    int b = bh >> 2, h = bh & 3;
#pragma unroll
    for (int r = 0; r < 2; r++) {
        int i = i0 + ty*2 + r;
        if (i < LL) {
            float2 lo = up2(acc[r][0]), hi = up2(acc[r][1]);
            *(float4*)(g_O + (b*LL + i)*DD + h*HD + tx*4) =
                make_float4(lo.x, lo.y, hi.x, hi.y);
        }
    }
}

// ---------------- K7: out = O @ Wo^T ---------------------------------------------
// grid (4, 15), block (16,16). 32-row x 64-col tiles, K=256.
__global__ void out_kernel(const float* __restrict__ Wo, float* __restrict__ out) {
    __shared__ __align__(16) float Os[32][20];
    __shared__ __align__(16) float Ws[16][68];
    int tx = threadIdx.x, ty = threadIdx.y;
    int tid = ty*16 + tx;
    int m0 = blockIdx.y*32, c0 = blockIdx.x*64;
    unsigned long long acc[2][2] = {};
    for (int k0 = 0; k0 < 256; k0 += 16) {
        if (tid < 128) {
            int ii = tid >> 2, f = tid & 3;
            int m = m0 + ii;
            float4 v = (m < NROW) ? ld4(g_O + m*256 + k0 + 4*f) : f4z();
            *(float4*)&Os[ii][4*f] = v;
        } else {
#pragma unroll
            for (int s2 = 0; s2 < 2; s2++) {
                int idx = (tid - 128) + 128*s2;
                int ll = idx >> 2, f = idx & 3;
                float4 w = ld4(Wo + (c0 + ll)*256 + k0 + 4*f);
                Ws[4*f+0][ll] = w.x; Ws[4*f+1][ll] = w.y;
                Ws[4*f+2][ll] = w.z; Ws[4*f+3][ll] = w.w;
            }
        }
        __syncthreads();
        inner16_2<20, 68>(&Os[0][0], &Ws[0][0], ty*2, tx*4, acc);
        __syncthreads();
    }
#pragma unroll
    for (int r = 0; r < 2; r++) {
        int m = m0 + ty*2 + r;
        if (m < NROW) {
            float2 lo = up2(acc[r][0]), hi = up2(acc[r][1]);
            *(float4*)(out + m*256 + c0 + tx*4) =
                make_float4(lo.x, lo.y, hi.x, hi.y);
        }
    }
}

// ---------------- launcher --------------------------------------------------------
extern "C" void kernel_launch(void* const* d_in, const int* in_sizes, int n_in,
                              void* d_out, int out_size) {
    const float* x  = (const float*)d_in[0];
    const float* Wq = (const float*)d_in[1];
    const float* Wk = (const float*)d_in[2];
    const float* Wv = (const float*)d_in[3];
    const float* Wo = (const float*)d_in[4];
    float* out = (float*)d_out;

    dim3 b16(16, 16), b168(16, 8);

    qkv_kernel<<<dim3(12, 15), b168>>>(x, Wq, Wk, Wv);
    s_kernel<<<dim3(4, 4, 8), b16>>>();
    a_kernel<<<dim3(36, 8), b16>>>();
    gemm_kernel<0><<<dim3(4, 8, 8), b16>>>();
    gemm_kernel<1><<<dim3(4, 8, 8), b16>>>();
    av_kernel<<<dim3(8, 8), b16>>>();
    out_kernel<<<dim3(4, 15), b16>>>(Wo, out);
}